// round 13
// baseline (speedup 1.0000x reference)
#include <cuda_runtime.h>

#define BATCH  8
#define SEQ    4096
#define DMODEL 512

// Grid = 2048 CTAs x 128 threads. Each CTA covers two sequence positions
// (two 64-thread halves); each thread owns 8 contiguous d's (32 bytes).
// Table gathers use 256-bit ld.global.nc.L2::evict_last.v4.b64 (ptxas on
// sm_103a only allows evict_last at 256-bit width) to pin the 65.5MB table
// in L2; output uses evict-first __stcs so the 67MB write-once stream
// doesn't thrash it. Steady-state goal: DRAM = writes only.

struct F8 { float4 lo, hi; };

__device__ __forceinline__ F8 ldg_evl_32B(const void* p) {
    unsigned long long a, b, c, d;
    asm volatile("ld.global.nc.L2::evict_last.v4.b64 {%0,%1,%2,%3}, [%4];"
                 : "=l"(a), "=l"(b), "=l"(c), "=l"(d) : "l"(p));
    F8 r;
    r.lo.x = __uint_as_float((unsigned)(a));
    r.lo.y = __uint_as_float((unsigned)(a >> 32));
    r.lo.z = __uint_as_float((unsigned)(b));
    r.lo.w = __uint_as_float((unsigned)(b >> 32));
    r.hi.x = __uint_as_float((unsigned)(c));
    r.hi.y = __uint_as_float((unsigned)(c >> 32));
    r.hi.z = __uint_as_float((unsigned)(d));
    r.hi.w = __uint_as_float((unsigned)(d >> 32));
    return r;
}

__global__ void __launch_bounds__(128)
embed_pe_kernel(const int* __restrict__ tokens,
                const float* __restrict__ table,
                float* __restrict__ out)
{
    const int t    = threadIdx.x;
    const int h    = t >> 6;            // 0/1: which position
    const int lane = t & 63;
    const int d0   = lane << 3;         // 0,8,...,504
    const int s    = (blockIdx.x << 1) + h;   // 0..4095

    // token ids (uniform per half -> broadcast LDG)
    int tok[BATCH];
#pragma unroll
    for (int b = 0; b < BATCH; ++b)
        tok[b] = __ldg(tokens + b * SEQ + s);

    // fire all 8 gathers (32B each), evict-last
    F8 e[BATCH];
#pragma unroll
    for (int b = 0; b < BATCH; ++b)
        e[b] = ldg_evl_32B(table + (size_t)tok[b] * DMODEL + d0);

    // PE for (s, d0..d0+7) in the shadow of the loads
    const float ps = (float)s;
    float pe[8];
#pragma unroll
    for (int j = 0; j < 8; ++j) {
        const float fi    = (float)(d0 + j);
        // 1/10000^(2*i/D) = exp2(-(2*i/D)*log2(10000))
        const float inv_w = exp2f(fi * (-2.0f / (float)DMODEL) * 13.287712379549449f);
        const float angle = ps * inv_w;
        pe[j] = ((d0 + j) & 1) ? cosf(angle) : sinf(angle);
    }

    // add + evict-first streaming stores (2 x 16B per row)
#pragma unroll
    for (int b = 0; b < BATCH; ++b) {
        float* op = out + ((size_t)(b * SEQ + s)) * DMODEL + d0;
        float4 o0, o1;
        o0.x = e[b].lo.x + pe[0];
        o0.y = e[b].lo.y + pe[1];
        o0.z = e[b].lo.z + pe[2];
        o0.w = e[b].lo.w + pe[3];
        o1.x = e[b].hi.x + pe[4];
        o1.y = e[b].hi.y + pe[5];
        o1.z = e[b].hi.z + pe[6];
        o1.w = e[b].hi.w + pe[7];
        __stcs(reinterpret_cast<float4*>(op),     o0);
        __stcs(reinterpret_cast<float4*>(op + 4), o1);
    }
}

extern "C" void kernel_launch(void* const* d_in, const int* in_sizes, int n_in,
                              void* d_out, int out_size)
{
    const int*   tokens = (const int*)d_in[0];   // [B, S] int32
    const float* table  = (const float*)d_in[1]; // [VOCAB, D] f32
    float*       out    = (float*)d_out;         // [B, S, D] f32
    (void)in_sizes; (void)n_in; (void)out_size;

    embed_pe_kernel<<<SEQ / 2, 128>>>(tokens, table, out);
}

// round 14
// speedup vs baseline: 1.3643x; 1.3643x over previous
#include <cuda_runtime.h>

#define BATCH  8
#define SEQ    4096
#define DMODEL 512

// Grid = 2048 CTAs x 128 threads; each CTA covers two positions (two
// 64-thread halves), each thread owns 8 contiguous d's (32 bytes).
// Blackwell 256-bit global accesses (v8.b32): halves the LDG/STG instruction
// count vs 128-bit at identical traffic. NO evict_last on gathers (R13
// evidence: pinning the table throttles the write-allocate stream in steady
// state -> +6us). Stores keep evict-first so the 67MB write-once stream
// doesn't displace the table.

struct F8 { float f[8]; };

__device__ __forceinline__ F8 ldg_nc_256(const void* p) {
    unsigned a0,a1,a2,a3,a4,a5,a6,a7;
    asm volatile("ld.global.nc.v8.b32 {%0,%1,%2,%3,%4,%5,%6,%7}, [%8];"
                 : "=r"(a0),"=r"(a1),"=r"(a2),"=r"(a3),
                   "=r"(a4),"=r"(a5),"=r"(a6),"=r"(a7) : "l"(p));
    F8 r;
    r.f[0]=__uint_as_float(a0); r.f[1]=__uint_as_float(a1);
    r.f[2]=__uint_as_float(a2); r.f[3]=__uint_as_float(a3);
    r.f[4]=__uint_as_float(a4); r.f[5]=__uint_as_float(a5);
    r.f[6]=__uint_as_float(a6); r.f[7]=__uint_as_float(a7);
    return r;
}

__device__ __forceinline__ void stg_ef_256(void* p, const float* v) {
    asm volatile("st.global.L2::evict_first.v8.b32 [%0], {%1,%2,%3,%4,%5,%6,%7,%8};"
                 :: "l"(p),
                    "r"(__float_as_uint(v[0])), "r"(__float_as_uint(v[1])),
                    "r"(__float_as_uint(v[2])), "r"(__float_as_uint(v[3])),
                    "r"(__float_as_uint(v[4])), "r"(__float_as_uint(v[5])),
                    "r"(__float_as_uint(v[6])), "r"(__float_as_uint(v[7]))
                 : "memory");
}

__global__ void __launch_bounds__(128)
embed_pe_kernel(const int* __restrict__ tokens,
                const float* __restrict__ table,
                float* __restrict__ out)
{
    const int t    = threadIdx.x;
    const int h    = t >> 6;                  // 0/1: which position
    const int lane = t & 63;
    const int d0   = lane << 3;               // 0,8,...,504
    const int s    = (blockIdx.x << 1) + h;   // 0..4095

    // token ids (uniform per half -> broadcast LDG)
    int tok[BATCH];
#pragma unroll
    for (int b = 0; b < BATCH; ++b)
        tok[b] = __ldg(tokens + b * SEQ + s);

    // fire all 8 gathers (32B each), default L2 policy
    F8 e[BATCH];
#pragma unroll
    for (int b = 0; b < BATCH; ++b)
        e[b] = ldg_nc_256(table + (size_t)tok[b] * DMODEL + d0);

    // PE for (s, d0..d0+7) in the shadow of the loads
    const float ps = (float)s;
    float pe[8];
#pragma unroll
    for (int j = 0; j < 8; ++j) {
        const float fi    = (float)(d0 + j);
        // 1/10000^(2*i/D) = exp2(-(2*i/D)*log2(10000))
        const float inv_w = exp2f(fi * (-2.0f / (float)DMODEL) * 13.287712379549449f);
        const float angle = ps * inv_w;
        pe[j] = ((d0 + j) & 1) ? cosf(angle) : sinf(angle);
    }

    // add + one 256-bit evict-first store per row
#pragma unroll
    for (int b = 0; b < BATCH; ++b) {
        float o[8];
#pragma unroll
        for (int j = 0; j < 8; ++j) o[j] = e[b].f[j] + pe[j];
        stg_ef_256(out + ((size_t)(b * SEQ + s)) * DMODEL + d0, o);
    }
}

extern "C" void kernel_launch(void* const* d_in, const int* in_sizes, int n_in,
                              void* d_out, int out_size)
{
    const int*   tokens = (const int*)d_in[0];   // [B, S] int32
    const float* table  = (const float*)d_in[1]; // [VOCAB, D] f32
    float*       out    = (float*)d_out;         // [B, S, D] f32
    (void)in_sizes; (void)n_in; (void)out_size;

    embed_pe_kernel<<<SEQ / 2, 128>>>(tokens, table, out);
}